// round 8
// baseline (speedup 1.0000x reference)
#include <cuda_runtime.h>
#include <cuda_bf16.h>
#include <math.h>
#include <stdint.h>

#define Bc  2
#define Ic  2048
#define Mc  2048
#define Dc  1024
#define Hc  16
#define Dhc 64
#define BHc 32   // Bc*Hc

// ---------------- scratch (static device globals; no allocs) ----------------
__device__ __nv_bfloat16 g_Qh[BHc * (size_t)Ic * Dhc];
__device__ __nv_bfloat16 g_Ql[BHc * (size_t)Ic * Dhc];
__device__ __nv_bfloat16 g_Kh[BHc * (size_t)Mc * Dhc];
__device__ __nv_bfloat16 g_Kl[BHc * (size_t)Mc * Dhc];
__device__ __nv_bfloat16 g_Vh[BHc * (size_t)Mc * Dhc];
__device__ __nv_bfloat16 g_Vl[BHc * (size_t)Mc * Dhc];
__device__ float  g_O[Bc * (size_t)Ic * Dc];     // [B,I,D] (pre-Wo)
__device__ float2 g_stats[BHc * Ic];             // (rowmax, 1/rowsum)

// ======================= mma.sync helpers (sm_80+ path) =====================
__device__ __forceinline__ uint32_t smem_u32(const void* p) {
    return (uint32_t)__cvta_generic_to_shared(p);
}
__device__ __forceinline__ void ldsm4(uint32_t addr, uint32_t* r) {
    asm volatile("ldmatrix.sync.aligned.m8n8.x4.shared.b16 {%0,%1,%2,%3}, [%4];"
                 : "=r"(r[0]), "=r"(r[1]), "=r"(r[2]), "=r"(r[3]) : "r"(addr));
}
__device__ __forceinline__ void ldsm4t(uint32_t addr, uint32_t* r) {
    asm volatile("ldmatrix.sync.aligned.m8n8.x4.trans.shared.b16 {%0,%1,%2,%3}, [%4];"
                 : "=r"(r[0]), "=r"(r[1]), "=r"(r[2]), "=r"(r[3]) : "r"(addr));
}
__device__ __forceinline__ void mma16816(float* c, const uint32_t* a, const uint32_t* b) {
    asm volatile(
        "mma.sync.aligned.m16n8k16.row.col.f32.bf16.bf16.f32 "
        "{%0,%1,%2,%3}, {%4,%5,%6,%7}, {%8,%9}, {%0,%1,%2,%3};"
        : "+f"(c[0]), "+f"(c[1]), "+f"(c[2]), "+f"(c[3])
        : "r"(a[0]), "r"(a[1]), "r"(a[2]), "r"(a[3]), "r"(b[0]), "r"(b[1]));
}
__device__ __forceinline__ void cvt_split(float x, float y,
                                          __nv_bfloat162& h, __nv_bfloat162& l) {
    __nv_bfloat16 hx = __float2bfloat16(x);
    __nv_bfloat16 hy = __float2bfloat16(y);
    h.x = hx; h.y = hy;
    l.x = __float2bfloat16(x - __bfloat162float(hx));
    l.y = __float2bfloat16(y - __bfloat162float(hy));
}
// fast exp on the FMA pipe (no MUFU)
__device__ __forceinline__ float fexp(float x) {
    float y = fmaxf(x * 1.4426950408889634f, -126.0f);
    float z = y + 12582912.0f;
    int   n = __float_as_int(z) - 0x4B400000;
    float r = y - (z - 12582912.0f);
    float w = r * 0.69314718055994531f;
    float p = fmaf(w, 1.3888889e-3f, 8.3333333e-3f);
    p = fmaf(w, p, 4.1666667e-2f);
    p = fmaf(w, p, 1.6666667e-1f);
    p = fmaf(w, p, 0.5f);
    p = fmaf(w, p, 1.0f);
    p = fmaf(w, p, 1.0f);
    return p * __int_as_float((n + 127) << 23);
}
__device__ __forceinline__ void cp16(uint32_t dst, const void* src) {
    asm volatile("cp.async.ca.shared.global [%0], [%1], 16;" :: "r"(dst), "l"(src));
}
#define CP_COMMIT() asm volatile("cp.async.commit_group;" ::: "memory")
#define CP_WAIT0()  asm volatile("cp.async.wait_group 0;" ::: "memory")

// ============ bf16-split tensor-core GEMM: C[4096x1024] = A @ W =============
#define BKg     32
#define NCHUNK  (Dc / BKg)          // 32
#define A_PITCH 80
#define B_PITCH 272
#define A_BUF   (128 * A_PITCH)
#define B_BUF   (BKg * B_PITCH)
#define OFF_AH  0
#define OFF_AL  (2 * A_BUF)
#define OFF_BH  (4 * A_BUF)
#define OFF_BL  (OFF_BH + 2 * B_BUF)
#define SMEM_GEMM (OFF_BL + 2 * B_BUF) // 75776

__device__ __forceinline__ void gemm_sm(const float* __restrict__ A,
                                        const float* __restrict__ W,
                                        float* __restrict__ Cout,
                                        __nv_bfloat16* __restrict__ Ch,
                                        __nv_bfloat16* __restrict__ Cl,
                                        float scale, bool splitout) {
    extern __shared__ char sm[];
    const uint32_t smb = smem_u32(sm);

    const int tid  = threadIdx.x;
    const int wid  = tid >> 5;
    const int lane = tid & 31;
    const int wr   = wid & 1;
    const int wc   = wid >> 1;
    const int row0 = blockIdx.y * 128;
    const int col0 = blockIdx.x * 128;

    int arow[4], ac4[4], wrow[4], wc4[4];
#pragma unroll
    for (int t = 0; t < 4; t++) {
        const int fi = tid + t * 256;
        arow[t] = fi >> 3;  ac4[t] = (fi & 7) * 4;
        wrow[t] = fi >> 5;  wc4[t] = (fi & 31) * 4;
    }

    float4 ra[4], rw[4];
    auto ld_chunk = [&](int k0) {
#pragma unroll
        for (int t = 0; t < 4; t++) {
            ra[t] = *(const float4*)(A + (size_t)(row0 + arow[t]) * Dc + k0 + ac4[t]);
            rw[t] = *(const float4*)(W + (size_t)(k0 + wrow[t]) * Dc + col0 + wc4[t]);
        }
    };
    auto st_chunk = [&](int buf) {
#pragma unroll
        for (int t = 0; t < 4; t++) {
            __nv_bfloat162 h0, l0, h1, l1;
            cvt_split(ra[t].x, ra[t].y, h0, l0);
            cvt_split(ra[t].z, ra[t].w, h1, l1);
            const int ao = buf * A_BUF + arow[t] * A_PITCH + ac4[t] * 2;
            *(__nv_bfloat162*)(sm + OFF_AH + ao)     = h0;
            *(__nv_bfloat162*)(sm + OFF_AH + ao + 4) = h1;
            *(__nv_bfloat162*)(sm + OFF_AL + ao)     = l0;
            *(__nv_bfloat162*)(sm + OFF_AL + ao + 4) = l1;
            cvt_split(rw[t].x, rw[t].y, h0, l0);
            cvt_split(rw[t].z, rw[t].w, h1, l1);
            const int bo = buf * B_BUF + wrow[t] * B_PITCH + wc4[t] * 2;
            *(__nv_bfloat162*)(sm + OFF_BH + bo)     = h0;
            *(__nv_bfloat162*)(sm + OFF_BH + bo + 4) = h1;
            *(__nv_bfloat162*)(sm + OFF_BL + bo)     = l0;
            *(__nv_bfloat162*)(sm + OFF_BL + bo + 4) = l1;
        }
    };

    float Cf[4][4][4];
#pragma unroll
    for (int mi = 0; mi < 4; mi++)
#pragma unroll
        for (int nf = 0; nf < 4; nf++)
#pragma unroll
            for (int j = 0; j < 4; j++) Cf[mi][nf][j] = 0.0f;

    ld_chunk(0);
    st_chunk(0);
    __syncthreads();

    const uint32_t a_r  = (uint32_t)(wr * 64 + (lane & 7) + ((lane >> 3) & 1) * 8);
    const uint32_t a_cb = (uint32_t)((lane >> 4) * 16);
    const uint32_t b_r  = (uint32_t)(((lane >> 3) & 1) * 8 + (lane & 7));
    const uint32_t b_cb = (uint32_t)((wc * 32 + ((lane >> 4) & 1) * 8) * 2);

    for (int c = 0; c < NCHUNK; c++) {
        if (c + 1 < NCHUNK) ld_chunk((c + 1) * BKg);
        const int buf = c & 1;
        const uint32_t abase = smb + buf * A_BUF;
        const uint32_t bbase = smb + buf * B_BUF;

#pragma unroll
        for (int ks = 0; ks < BKg; ks += 16) {
            uint32_t ah[4][4], al[4][4], bh[4][2], bl[4][2];
#pragma unroll
            for (int mi = 0; mi < 4; mi++) {
                const uint32_t ao = (a_r + mi * 16) * A_PITCH + ks * 2 + a_cb;
                ldsm4(abase + OFF_AH + ao, ah[mi]);
                ldsm4(abase + OFF_AL + ao, al[mi]);
            }
#pragma unroll
            for (int half = 0; half < 2; half++) {
                const uint32_t bo = (ks + b_r) * B_PITCH + b_cb + half * 32;
                uint32_t t4[4];
                ldsm4t(bbase + OFF_BH + bo, t4);
                bh[half * 2][0] = t4[0]; bh[half * 2][1] = t4[1];
                bh[half * 2 + 1][0] = t4[2]; bh[half * 2 + 1][1] = t4[3];
                ldsm4t(bbase + OFF_BL + bo, t4);
                bl[half * 2][0] = t4[0]; bl[half * 2][1] = t4[1];
                bl[half * 2 + 1][0] = t4[2]; bl[half * 2 + 1][1] = t4[3];
            }
#pragma unroll
            for (int mi = 0; mi < 4; mi++)
#pragma unroll
                for (int nf = 0; nf < 4; nf++) {
                    mma16816(Cf[mi][nf], ah[mi], bh[nf]);
                    mma16816(Cf[mi][nf], al[mi], bh[nf]);
                    mma16816(Cf[mi][nf], ah[mi], bl[nf]);
                }
        }
        if (c + 1 < NCHUNK) st_chunk(1 - buf);
        __syncthreads();
    }

#pragma unroll
    for (int mi = 0; mi < 4; mi++) {
        const int rg = row0 + wr * 64 + mi * 16 + (lane >> 2);
#pragma unroll
        for (int nf = 0; nf < 4; nf++) {
            const int cg = col0 + wc * 32 + nf * 8 + (lane & 3) * 2;
            float2 v0 = make_float2(Cf[mi][nf][0] * scale, Cf[mi][nf][1] * scale);
            float2 v1 = make_float2(Cf[mi][nf][2] * scale, Cf[mi][nf][3] * scale);
            if (splitout) {
                const int h = cg >> 6, d = cg & 63;
                const int b0_ = rg >> 11, i0_ = rg & 2047;
                const int b1_ = (rg + 8) >> 11, i1_ = (rg + 8) & 2047;
                const size_t idx0 = (((size_t)(b0_ * Hc + h) * Ic + i0_) << 6) + d;
                const size_t idx1 = (((size_t)(b1_ * Hc + h) * Ic + i1_) << 6) + d;
                __nv_bfloat162 hh, ll;
                cvt_split(v0.x, v0.y, hh, ll);
                *(__nv_bfloat162*)(Ch + idx0) = hh;
                *(__nv_bfloat162*)(Cl + idx0) = ll;
                cvt_split(v1.x, v1.y, hh, ll);
                *(__nv_bfloat162*)(Ch + idx1) = hh;
                *(__nv_bfloat162*)(Cl + idx1) = ll;
            } else {
                *(float2*)&Cout[(size_t)rg * Dc + cg]       = v0;
                *(float2*)&Cout[(size_t)(rg + 8) * Dc + cg] = v1;
            }
        }
    }
}

__global__ __launch_bounds__(256) void qkv_kernel(
    const float* __restrict__ input, const float* __restrict__ memory,
    const float* __restrict__ Wq, const float* __restrict__ Wk,
    const float* __restrict__ Wv)
{
    if (blockIdx.z == 0)       gemm_sm(input,  Wq, nullptr, g_Qh, g_Ql, 0.125f, true);
    else if (blockIdx.z == 1)  gemm_sm(memory, Wk, nullptr, g_Kh, g_Kl, 1.0f,   true);
    else                       gemm_sm(memory, Wv, nullptr, g_Vh, g_Vl, 1.0f,   true);
}

__global__ __launch_bounds__(256) void out_kernel(
    const float* __restrict__ Wo, float* __restrict__ out)
{
    gemm_sm(g_O, Wo, out, nullptr, nullptr, 1.0f, false);
}

// ======= logits: S = Q K^T + bias -> raw align write + online (m, 1/l) ======
#define LP 144
#define LKBUF 9216
__global__ __launch_bounds__(256) void logits_kernel(
    const float* __restrict__ bias, float* __restrict__ align)
{
    __shared__ char sm[4 * LKBUF];
    const uint32_t smb = smem_u32(sm);
    const int tid = threadIdx.x, wid = tid >> 5, lane = tid & 31;
    const int bh = blockIdx.y, b = bh >> 4;
    const int i0 = blockIdx.x * 128;

#pragma unroll
    for (int t = 0; t < 4; t++) {
        const int fi = tid + t * 256;
        const int r = fi >> 3, c = fi & 7;
        const size_t gi = ((size_t)bh * Ic + i0 + r) * 64;
        *(uint4*)(sm + r * LP + c * 16)             = *((const uint4*)(g_Qh + gi) + c);
        *(uint4*)(sm + 2 * LKBUF + r * LP + c * 16) = *((const uint4*)(g_Ql + gi) + c);
    }
    __syncthreads();

    uint32_t qh[4][4], ql[4][4];
    const uint32_t a_off = (uint32_t)((wid * 16 + (lane & 7) + ((lane >> 3) & 1) * 8) * LP
                                      + (lane >> 4) * 16);
#pragma unroll
    for (int ks = 0; ks < 4; ks++) {
        ldsm4(smb + a_off + ks * 32, qh[ks]);
        ldsm4(smb + 2 * LKBUF + a_off + ks * 32, ql[ks]);
    }
    __syncthreads();

    auto stageK = [&](int m0, int base) {
#pragma unroll
        for (int t = 0; t < 4; t++) {
            const int fi = tid + t * 256;
            const int r = (fi >> 3) & 63, c = fi & 7;
            const __nv_bfloat16* src = (t < 2 ? g_Kh : g_Kl);
            const int off = (t < 2 ? 0 : LKBUF);
            cp16(smb + base + off + r * LP + c * 16,
                 src + ((size_t)bh * Mc + m0 + r) * 64 + c * 8);
        }
    };
    stageK(0, 0);
    CP_COMMIT();
    CP_WAIT0();
    __syncthreads();

    const int r0 = lane >> 2;
    const int irow0 = i0 + wid * 16 + r0;
    float m_run[2] = {-3.402823466e38f, -3.402823466e38f};
    float l_run[2] = {0.0f, 0.0f};

    const uint32_t b_row = (uint32_t)((lane & 7) + (lane >> 4) * 8);
    const uint32_t b_kb  = (uint32_t)(((lane >> 3) & 1) * 16);

    for (int c = 0; c < 32; c++) {
        const int m0 = c * 64;
        const int buf = (c & 1) * 2 * LKBUF;
        if (c + 1 < 32) {
            stageK((c + 1) * 64, (1 - (c & 1)) * 2 * LKBUF);
            CP_COMMIT();
        }

        float Cf[8][4];
#pragma unroll
        for (int nf = 0; nf < 8; nf++)
#pragma unroll
            for (int j = 0; j < 4; j++) Cf[nf][j] = 0.0f;

#pragma unroll
        for (int ks = 0; ks < 4; ks++) {
            uint32_t kh[8][2], kl[8][2];
#pragma unroll
            for (int mg = 0; mg < 4; mg++) {
                const uint32_t baddr = smb + buf + (mg * 16 + b_row) * LP + ks * 32 + b_kb;
                uint32_t t4[4];
                ldsm4(baddr, t4);
                kh[mg * 2][0] = t4[0]; kh[mg * 2][1] = t4[1];
                kh[mg * 2 + 1][0] = t4[2]; kh[mg * 2 + 1][1] = t4[3];
                ldsm4(baddr + LKBUF, t4);
                kl[mg * 2][0] = t4[0]; kl[mg * 2][1] = t4[1];
                kl[mg * 2 + 1][0] = t4[2]; kl[mg * 2 + 1][1] = t4[3];
            }
#pragma unroll
            for (int nf = 0; nf < 8; nf++) {
                mma16816(Cf[nf], qh[ks], kh[nf]);
                mma16816(Cf[nf], ql[ks], kh[nf]);
                mma16816(Cf[nf], qh[ks], kl[nf]);
            }
        }

        // bias add + raw S store + online stats
        float mx[2] = {-3.402823466e38f, -3.402823466e38f};
#pragma unroll
        for (int nf = 0; nf < 8; nf++) {
            const int col = m0 + nf * 8 + (lane & 3) * 2;
            const float2 bv0 = *(const float2*)(bias + ((size_t)(b * Ic) + irow0) * Mc + col);
            const float2 bv1 = *(const float2*)(bias + ((size_t)(b * Ic) + irow0 + 8) * Mc + col);
            Cf[nf][0] += bv0.x; Cf[nf][1] += bv0.y;
            Cf[nf][2] += bv1.x; Cf[nf][3] += bv1.y;
            *(float2*)(align + ((size_t)(bh * Ic) + irow0) * Mc + col) =
                make_float2(Cf[nf][0], Cf[nf][1]);
            *(float2*)(align + ((size_t)(bh * Ic) + irow0 + 8) * Mc + col) =
                make_float2(Cf[nf][2], Cf[nf][3]);
            mx[0] = fmaxf(mx[0], fmaxf(Cf[nf][0], Cf[nf][1]));
            mx[1] = fmaxf(mx[1], fmaxf(Cf[nf][2], Cf[nf][3]));
        }
#pragma unroll
        for (int rr = 0; rr < 2; rr++) {
            mx[rr] = fmaxf(mx[rr], __shfl_xor_sync(0xffffffffu, mx[rr], 1));
            mx[rr] = fmaxf(mx[rr], __shfl_xor_sync(0xffffffffu, mx[rr], 2));
            const float mnew = fmaxf(m_run[rr], mx[rr]);
            const float sc = fexp(m_run[rr] - mnew);
            float ps = 0.0f;
#pragma unroll
            for (int nf = 0; nf < 8; nf++)
                ps += fexp(Cf[nf][rr * 2] - mnew) + fexp(Cf[nf][rr * 2 + 1] - mnew);
            ps += __shfl_xor_sync(0xffffffffu, ps, 1);
            ps += __shfl_xor_sync(0xffffffffu, ps, 2);
            l_run[rr] = l_run[rr] * sc + ps;
            m_run[rr] = mnew;
        }

        if (c + 1 < 32) {
            CP_WAIT0();
            __syncthreads();
        }
    }

    if ((lane & 3) == 0) {
#pragma unroll
        for (int rr = 0; rr < 2; rr++) {
            g_stats[bh * Ic + irow0 + rr * 8] = make_float2(m_run[rr], 1.0f / l_run[rr]);
        }
    }
}

// == pv: p = exp(s - m)/l -> align (final); O = P V (3-term, register P) =====
#define PVARR 9216             // one 64x64 bf16 array at pitch LP
#define PVB   (2 * PVARR)      // Vh, Vl
__global__ __launch_bounds__(256) void pv_kernel(float* __restrict__ align)
{
    __shared__ char smp[2 * PVB];     // 36864: double-buffered Vh+Vl
    const uint32_t smb = smem_u32(smp);
    const int tid = threadIdx.x, wid = tid >> 5, lane = tid & 31;
    const int bh = blockIdx.y, b = bh >> 4, h = bh & 15;
    const int i0 = blockIdx.x * 128;

    const int r0 = lane >> 2;
    const int irow0 = i0 + wid * 16 + r0;
    const float2 st0 = g_stats[bh * Ic + irow0];
    const float2 st1 = g_stats[bh * Ic + irow0 + 8];

    auto stageV = [&](int m0, int base) {
#pragma unroll
        for (int t = 0; t < 4; t++) {
            const int fi = tid + t * 256;        // 0..1023
            const int w = fi & 511;
            const int r = w >> 3, cc = w & 7;
            const __nv_bfloat16* src = (t < 2 ? g_Vh : g_Vl);
            const int off = (t < 2 ? 0 : PVARR);
            cp16(smb + base + off + r * LP + cc * 16,
                 src + ((size_t)bh * Mc + m0 + r) * 64 + cc * 8);
        }
    };
    stageV(0, 0);
    CP_COMMIT();
    CP_WAIT0();
    __syncthreads();

    float Oacc[8][4];
#pragma unroll
    for (int nf = 0; nf < 8; nf++)
#pragma unroll
        for (int j = 0; j < 4; j++) Oacc[nf][j] = 0.0f;

    const uint32_t vb_r = (uint32_t)(((lane >> 3) & 1) * 8 + (lane & 7));
    const uint32_t vb_c = (uint32_t)(((lane >> 4) & 1) * 16);

    float* arow0 = align + ((size_t)(bh * Ic) + irow0) * Mc;
    float* arow1 = align + ((size_t)(bh * Ic) + irow0 + 8) * Mc;

    for (int c = 0; c < 32; c++) {
        const int m0 = c * 64;
        const uint32_t buf = (uint32_t)((c & 1) * PVB);
        if (c + 1 < 32) {
            stageV((c + 1) * 64, (1 - (c & 1)) * PVB);
            CP_COMMIT();
        }

        // load raw S, normalize, write final align, keep p in Cf
        float Cf[8][4];
#pragma unroll
        for (int nf = 0; nf < 8; nf++) {
            const int col = m0 + nf * 8 + (lane & 3) * 2;
            const float2 s0 = *(const float2*)(arow0 + col);
            const float2 s1 = *(const float2*)(arow1 + col);
            Cf[nf][0] = s0.x; Cf[nf][1] = s0.y;
            Cf[nf][2] = s1.x; Cf[nf][3] = s1.y;
        }
#pragma unroll
        for (int nf = 0; nf < 8; nf++) {
            const int col = m0 + nf * 8 + (lane & 3) * 2;
            float p0 = fexp(Cf[nf][0] - st0.x) * st0.y;
            float p1 = fexp(Cf[nf][1] - st0.x) * st0.y;
            float p2 = fexp(Cf[nf][2] - st1.x) * st1.y;
            float p3 = fexp(Cf[nf][3] - st1.x) * st1.y;
            Cf[nf][0] = p0; Cf[nf][1] = p1; Cf[nf][2] = p2; Cf[nf][3] = p3;
            *(float2*)(arow0 + col) = make_float2(p0, p1);
            *(float2*)(arow1 + col) = make_float2(p2, p3);
        }

        // O += P V (3-term): re-pack C frags as split A frags, V from smem
#pragma unroll
        for (int kk = 0; kk < 4; kk++) {
            uint32_t ah[4], al[4];
            __nv_bfloat162 hh, ll;
            cvt_split(Cf[2 * kk][0], Cf[2 * kk][1], hh, ll);
            ah[0] = *(uint32_t*)&hh; al[0] = *(uint32_t*)&ll;
            cvt_split(Cf[2 * kk][2], Cf[2 * kk][3], hh, ll);
            ah[1] = *(uint32_t*)&hh; al[1] = *(uint32_t*)&ll;
            cvt_split(Cf[2 * kk + 1][0], Cf[2 * kk + 1][1], hh, ll);
            ah[2] = *(uint32_t*)&hh; al[2] = *(uint32_t*)&ll;
            cvt_split(Cf[2 * kk + 1][2], Cf[2 * kk + 1][3], hh, ll);
            ah[3] = *(uint32_t*)&hh; al[3] = *(uint32_t*)&ll;

            uint32_t vh[8][2], vl[8][2];
#pragma unroll
            for (int q = 0; q < 4; q++) {
                const uint32_t vaddr = smb + buf + (kk * 16 + vb_r) * LP + q * 32 + vb_c;
                uint32_t t4[4];
                ldsm4t(vaddr, t4);
                vh[q * 2][0] = t4[0]; vh[q * 2][1] = t4[1];
                vh[q * 2 + 1][0] = t4[2]; vh[q * 2 + 1][1] = t4[3];
                ldsm4t(vaddr + PVARR, t4);
                vl[q * 2][0] = t4[0]; vl[q * 2][1] = t4[1];
                vl[q * 2 + 1][0] = t4[2]; vl[q * 2 + 1][1] = t4[3];
            }
#pragma unroll
            for (int nf = 0; nf < 8; nf++) {
                mma16816(Oacc[nf], ah, vh[nf]);
                mma16816(Oacc[nf], al, vh[nf]);
                mma16816(Oacc[nf], ah, vl[nf]);
            }
        }

        if (c + 1 < 32) {
            CP_WAIT0();
            __syncthreads();
        }
    }

#pragma unroll
    for (int nf = 0; nf < 8; nf++) {
        const int d = nf * 8 + (lane & 3) * 2;
        *(float2*)(g_O + ((size_t)(b * Ic) + irow0) * Dc + h * 64 + d) =
            make_float2(Oacc[nf][0], Oacc[nf][1]);
        *(float2*)(g_O + ((size_t)(b * Ic) + irow0 + 8) * Dc + h * 64 + d) =
            make_float2(Oacc[nf][2], Oacc[nf][3]);
    }
}

// ---------------- launch ----------------------------------------------------
extern "C" void kernel_launch(void* const* d_in, const int* in_sizes, int n_in,
                              void* d_out, int out_size)
{
    const float* input  = (const float*)d_in[0];
    const float* memory = (const float*)d_in[1];
    const float* bias   = (const float*)d_in[2];
    const float* Wq     = (const float*)d_in[3];
    const float* Wk     = (const float*)d_in[4];
    const float* Wv     = (const float*)d_in[5];
    const float* Wo     = (const float*)d_in[6];

    float* out   = (float*)d_out;                  // [B,I,D]
    float* align = out + (size_t)Bc * Ic * Dc;     // [B,H,I,M]

    static int attr_done = 0;
    if (!attr_done) {
        cudaFuncSetAttribute(qkv_kernel, cudaFuncAttributeMaxDynamicSharedMemorySize, SMEM_GEMM);
        cudaFuncSetAttribute(out_kernel, cudaFuncAttributeMaxDynamicSharedMemorySize, SMEM_GEMM);
        attr_done = 1;
    }

    dim3 gqkv(Dc / 128, (Bc * Ic) / 128, 3);       // (8, 32, 3)
    qkv_kernel<<<gqkv, 256, SMEM_GEMM>>>(input, memory, Wq, Wk, Wv);

    logits_kernel<<<dim3(Ic / 128, BHc), 256>>>(bias, align);

    pv_kernel<<<dim3(Ic / 128, BHc), 256>>>(align);

    out_kernel<<<dim3(Dc / 128, (Bc * Ic) / 128), 256, SMEM_GEMM>>>(Wo, out);
}

// round 9
// speedup vs baseline: 1.5705x; 1.5705x over previous
#include <cuda_runtime.h>
#include <cuda_bf16.h>
#include <math.h>
#include <stdint.h>

#define Bc  2
#define Ic  2048
#define Mc  2048
#define Dc  1024
#define Hc  16
#define Dhc 64
#define BHc 32   // Bc*Hc
#define IN_N ((size_t)Bc * Ic * Dc)   // 4194304
#define W_N  ((size_t)Dc * Dc)        // 1048576

// ---------------- scratch (static device globals; no allocs) ----------------
__device__ __nv_bfloat16 g_Inh[IN_N],  g_Inl[IN_N];
__device__ __nv_bfloat16 g_Memh[IN_N], g_Meml[IN_N];
__device__ __nv_bfloat16 g_Wqh[W_N], g_Wql[W_N];
__device__ __nv_bfloat16 g_Wkh[W_N], g_Wkl[W_N];
__device__ __nv_bfloat16 g_Wvh[W_N], g_Wvl[W_N];
__device__ __nv_bfloat16 g_Woh[W_N], g_Wol[W_N];
__device__ __nv_bfloat16 g_Qh[BHc * (size_t)Ic * Dhc], g_Ql[BHc * (size_t)Ic * Dhc];
__device__ __nv_bfloat16 g_Kh[BHc * (size_t)Mc * Dhc], g_Kl[BHc * (size_t)Mc * Dhc];
__device__ __nv_bfloat16 g_Vh[BHc * (size_t)Mc * Dhc], g_Vl[BHc * (size_t)Mc * Dhc];
__device__ __nv_bfloat16 g_Oh[IN_N], g_Ol[IN_N];    // attention out, split
__device__ float2 g_stats[BHc * Ic];                // (rowmax, 1/rowsum)

// ======================= mma.sync helpers (sm_80+ path) =====================
__device__ __forceinline__ uint32_t smem_u32(const void* p) {
    return (uint32_t)__cvta_generic_to_shared(p);
}
__device__ __forceinline__ void ldsm4(uint32_t addr, uint32_t* r) {
    asm volatile("ldmatrix.sync.aligned.m8n8.x4.shared.b16 {%0,%1,%2,%3}, [%4];"
                 : "=r"(r[0]), "=r"(r[1]), "=r"(r[2]), "=r"(r[3]) : "r"(addr));
}
__device__ __forceinline__ void ldsm4t(uint32_t addr, uint32_t* r) {
    asm volatile("ldmatrix.sync.aligned.m8n8.x4.trans.shared.b16 {%0,%1,%2,%3}, [%4];"
                 : "=r"(r[0]), "=r"(r[1]), "=r"(r[2]), "=r"(r[3]) : "r"(addr));
}
__device__ __forceinline__ void mma16816(float* c, const uint32_t* a, const uint32_t* b) {
    asm volatile(
        "mma.sync.aligned.m16n8k16.row.col.f32.bf16.bf16.f32 "
        "{%0,%1,%2,%3}, {%4,%5,%6,%7}, {%8,%9}, {%0,%1,%2,%3};"
        : "+f"(c[0]), "+f"(c[1]), "+f"(c[2]), "+f"(c[3])
        : "r"(a[0]), "r"(a[1]), "r"(a[2]), "r"(a[3]), "r"(b[0]), "r"(b[1]));
}
__device__ __forceinline__ void cvt_split(float x, float y,
                                          __nv_bfloat162& h, __nv_bfloat162& l) {
    __nv_bfloat16 hx = __float2bfloat16(x);
    __nv_bfloat16 hy = __float2bfloat16(y);
    h.x = hx; h.y = hy;
    l.x = __float2bfloat16(x - __bfloat162float(hx));
    l.y = __float2bfloat16(y - __bfloat162float(hy));
}
// fast exp on the FMA pipe (no MUFU)
__device__ __forceinline__ float fexp(float x) {
    float y = fmaxf(x * 1.4426950408889634f, -126.0f);
    float z = y + 12582912.0f;
    int   n = __float_as_int(z) - 0x4B400000;
    float r = y - (z - 12582912.0f);
    float w = r * 0.69314718055994531f;
    float p = fmaf(w, 1.3888889e-3f, 8.3333333e-3f);
    p = fmaf(w, p, 4.1666667e-2f);
    p = fmaf(w, p, 1.6666667e-1f);
    p = fmaf(w, p, 0.5f);
    p = fmaf(w, p, 1.0f);
    p = fmaf(w, p, 1.0f);
    return p * __int_as_float((n + 127) << 23);
}
__device__ __forceinline__ void cp16(uint32_t dst, const void* src) {
    asm volatile("cp.async.ca.shared.global [%0], [%1], 16;" :: "r"(dst), "l"(src));
}
#define CP_COMMIT() asm volatile("cp.async.commit_group;" ::: "memory")
#define CP_WAIT0()  asm volatile("cp.async.wait_group 0;" ::: "memory")

// ============== split_kernel: fp32 -> (bf16 hi, bf16 lo) once ===============
__global__ __launch_bounds__(256) void split_kernel(
    const float* __restrict__ input, const float* __restrict__ memory,
    const float* __restrict__ Wq, const float* __restrict__ Wk,
    const float* __restrict__ Wv, const float* __restrict__ Wo)
{
    const float* src; __nv_bfloat16 *dh, *dl; size_t n;
    switch (blockIdx.y) {
        case 0:  src = input;  dh = g_Inh;  dl = g_Inl;  n = IN_N; break;
        case 1:  src = memory; dh = g_Memh; dl = g_Meml; n = IN_N; break;
        case 2:  src = Wq; dh = g_Wqh; dl = g_Wql; n = W_N; break;
        case 3:  src = Wk; dh = g_Wkh; dl = g_Wkl; n = W_N; break;
        case 4:  src = Wv; dh = g_Wvh; dl = g_Wvl; n = W_N; break;
        default: src = Wo; dh = g_Woh; dl = g_Wol; n = W_N; break;
    }
    for (size_t i = ((size_t)blockIdx.x * 256 + threadIdx.x) * 4; i < n;
         i += (size_t)gridDim.x * 1024) {
        float4 v = *(const float4*)(src + i);
        __nv_bfloat162 h0, l0, h1, l1;
        cvt_split(v.x, v.y, h0, l0);
        cvt_split(v.z, v.w, h1, l1);
        *(__nv_bfloat162*)(dh + i)     = h0;
        *(__nv_bfloat162*)(dh + i + 2) = h1;
        *(__nv_bfloat162*)(dl + i)     = l0;
        *(__nv_bfloat162*)(dl + i + 2) = l1;
    }
}

// ======= bf16-split tensor-core GEMM (pre-split operands, cp.async) =========
#define BKg     32
#define NCHUNK  (Dc / BKg)          // 32
#define A_PITCH 80
#define B_PITCH 272
#define A_BUF   (128 * A_PITCH)
#define B_BUF   (BKg * B_PITCH)
#define OFF_AH  0
#define OFF_AL  (2 * A_BUF)
#define OFF_BH  (4 * A_BUF)
#define OFF_BL  (OFF_BH + 2 * B_BUF)
#define SMEM_GEMM (OFF_BL + 2 * B_BUF) // 75776

__device__ __forceinline__ void gemm_bf(
    const __nv_bfloat16* __restrict__ Ah_g, const __nv_bfloat16* __restrict__ Al_g,
    const __nv_bfloat16* __restrict__ Wh_g, const __nv_bfloat16* __restrict__ Wl_g,
    float* __restrict__ Cout,
    __nv_bfloat16* __restrict__ Ch, __nv_bfloat16* __restrict__ Cl,
    float scale, bool splitout)
{
    extern __shared__ char sm[];
    const uint32_t smb = smem_u32(sm);

    const int tid  = threadIdx.x;
    const int wid  = tid >> 5;
    const int lane = tid & 31;
    const int wr   = wid & 1;
    const int wc   = wid >> 1;
    const int row0 = blockIdx.y * 128;
    const int col0 = blockIdx.x * 128;

    auto stage = [&](int k0, int buf) {
#pragma unroll
        for (int t = 0; t < 2; t++) {
            const int idx = tid + t * 256;               // 0..511
            const int ar = idx >> 2, ac = (idx & 3) * 16;
            const size_t aoff = ((size_t)(row0 + ar) * Dc + k0) * 2 + ac;
            cp16(smb + OFF_AH + buf * A_BUF + ar * A_PITCH + ac, (const char*)Ah_g + aoff);
            cp16(smb + OFF_AL + buf * A_BUF + ar * A_PITCH + ac, (const char*)Al_g + aoff);
            const int br = idx >> 4, bc = (idx & 15) * 16;
            const size_t boff = ((size_t)(k0 + br) * Dc + col0) * 2 + bc;
            cp16(smb + OFF_BH + buf * B_BUF + br * B_PITCH + bc, (const char*)Wh_g + boff);
            cp16(smb + OFF_BL + buf * B_BUF + br * B_PITCH + bc, (const char*)Wl_g + boff);
        }
    };

    float Cf[4][4][4];
#pragma unroll
    for (int mi = 0; mi < 4; mi++)
#pragma unroll
        for (int nf = 0; nf < 4; nf++)
#pragma unroll
            for (int j = 0; j < 4; j++) Cf[mi][nf][j] = 0.0f;

    stage(0, 0);
    CP_COMMIT();
    CP_WAIT0();
    __syncthreads();

    const uint32_t a_r  = (uint32_t)(wr * 64 + (lane & 7) + ((lane >> 3) & 1) * 8);
    const uint32_t a_cb = (uint32_t)((lane >> 4) * 16);
    const uint32_t b_r  = (uint32_t)(((lane >> 3) & 1) * 8 + (lane & 7));
    const uint32_t b_cb = (uint32_t)((wc * 32 + ((lane >> 4) & 1) * 8) * 2);

    for (int c = 0; c < NCHUNK; c++) {
        const int buf = c & 1;
        if (c + 1 < NCHUNK) {
            stage((c + 1) * BKg, 1 - buf);
            CP_COMMIT();
        }
        const uint32_t abase = smb + buf * A_BUF;
        const uint32_t bbase = smb + buf * B_BUF;

#pragma unroll
        for (int ks = 0; ks < BKg; ks += 16) {
            uint32_t ah[4][4], al[4][4], bh[4][2], bl[4][2];
#pragma unroll
            for (int mi = 0; mi < 4; mi++) {
                const uint32_t ao = (a_r + mi * 16) * A_PITCH + ks * 2 + a_cb;
                ldsm4(abase + OFF_AH + ao, ah[mi]);
                ldsm4(abase + OFF_AL + ao, al[mi]);
            }
#pragma unroll
            for (int half = 0; half < 2; half++) {
                const uint32_t bo = (ks + b_r) * B_PITCH + b_cb + half * 32;
                uint32_t t4[4];
                ldsm4t(bbase + OFF_BH + bo, t4);
                bh[half * 2][0] = t4[0]; bh[half * 2][1] = t4[1];
                bh[half * 2 + 1][0] = t4[2]; bh[half * 2 + 1][1] = t4[3];
                ldsm4t(bbase + OFF_BL + bo, t4);
                bl[half * 2][0] = t4[0]; bl[half * 2][1] = t4[1];
                bl[half * 2 + 1][0] = t4[2]; bl[half * 2 + 1][1] = t4[3];
            }
#pragma unroll
            for (int mi = 0; mi < 4; mi++)
#pragma unroll
                for (int nf = 0; nf < 4; nf++) {
                    mma16816(Cf[mi][nf], ah[mi], bh[nf]);
                    mma16816(Cf[mi][nf], al[mi], bh[nf]);
                    mma16816(Cf[mi][nf], ah[mi], bl[nf]);
                }
        }
        if (c + 1 < NCHUNK) {
            CP_WAIT0();
            __syncthreads();
        }
    }

#pragma unroll
    for (int mi = 0; mi < 4; mi++) {
        const int rg = row0 + wr * 64 + mi * 16 + (lane >> 2);
#pragma unroll
        for (int nf = 0; nf < 4; nf++) {
            const int cg = col0 + wc * 32 + nf * 8 + (lane & 3) * 2;
            float2 v0 = make_float2(Cf[mi][nf][0] * scale, Cf[mi][nf][1] * scale);
            float2 v1 = make_float2(Cf[mi][nf][2] * scale, Cf[mi][nf][3] * scale);
            if (splitout) {
                const int h = cg >> 6, d = cg & 63;
                const int b0_ = rg >> 11, i0_ = rg & 2047;
                const int b1_ = (rg + 8) >> 11, i1_ = (rg + 8) & 2047;
                const size_t idx0 = (((size_t)(b0_ * Hc + h) * Ic + i0_) << 6) + d;
                const size_t idx1 = (((size_t)(b1_ * Hc + h) * Ic + i1_) << 6) + d;
                __nv_bfloat162 hh, ll;
                cvt_split(v0.x, v0.y, hh, ll);
                *(__nv_bfloat162*)(Ch + idx0) = hh;
                *(__nv_bfloat162*)(Cl + idx0) = ll;
                cvt_split(v1.x, v1.y, hh, ll);
                *(__nv_bfloat162*)(Ch + idx1) = hh;
                *(__nv_bfloat162*)(Cl + idx1) = ll;
            } else {
                *(float2*)&Cout[(size_t)rg * Dc + cg]       = v0;
                *(float2*)&Cout[(size_t)(rg + 8) * Dc + cg] = v1;
            }
        }
    }
}

__global__ __launch_bounds__(256, 2) void qkv_kernel()
{
    if (blockIdx.z == 0)
        gemm_bf(g_Inh, g_Inl, g_Wqh, g_Wql, nullptr, g_Qh, g_Ql, 0.125f, true);
    else if (blockIdx.z == 1)
        gemm_bf(g_Memh, g_Meml, g_Wkh, g_Wkl, nullptr, g_Kh, g_Kl, 1.0f, true);
    else
        gemm_bf(g_Memh, g_Meml, g_Wvh, g_Wvl, nullptr, g_Vh, g_Vl, 1.0f, true);
}

__global__ __launch_bounds__(256, 2) void out_kernel(float* __restrict__ out)
{
    gemm_bf(g_Oh, g_Ol, g_Woh, g_Wol, out, nullptr, nullptr, 1.0f, false);
}

// ======= logits (EXACT R4): S = QK^T + bias -> raw align + (m, 1/l) =========
#define LP 144
#define LKBUF 9216
__global__ __launch_bounds__(256) void logits_kernel(
    const float* __restrict__ bias, float* __restrict__ align)
{
    __shared__ char sm[4 * LKBUF];
    const uint32_t smb = smem_u32(sm);
    const int tid = threadIdx.x, wid = tid >> 5, lane = tid & 31;
    const int bh = blockIdx.y, b = bh >> 4;
    const int i0 = blockIdx.x * 128;

#pragma unroll
    for (int t = 0; t < 4; t++) {
        const int fi = tid + t * 256;
        const int r = fi >> 3, c = fi & 7;
        const size_t gi = ((size_t)bh * Ic + i0 + r) * 64;
        *(uint4*)(sm + r * LP + c * 16)             = *((const uint4*)(g_Qh + gi) + c);
        *(uint4*)(sm + 2 * LKBUF + r * LP + c * 16) = *((const uint4*)(g_Ql + gi) + c);
    }
    __syncthreads();

    uint32_t qh[4][4], ql[4][4];
    const uint32_t a_off = (uint32_t)((wid * 16 + (lane & 7) + ((lane >> 3) & 1) * 8) * LP
                                      + (lane >> 4) * 16);
#pragma unroll
    for (int ks = 0; ks < 4; ks++) {
        ldsm4(smb + a_off + ks * 32, qh[ks]);
        ldsm4(smb + 2 * LKBUF + a_off + ks * 32, ql[ks]);
    }
    __syncthreads();

    auto stageK = [&](int m0, int base) {
#pragma unroll
        for (int t = 0; t < 2; t++) {
            const int fi = tid + t * 256;        // 0..511
            const int r = fi >> 3, c = fi & 7;
            const size_t gi = ((size_t)bh * Mc + m0 + r) * 64;
            *(uint4*)(sm + base + r * LP + c * 16)         = *((const uint4*)(g_Kh + gi) + c);
            *(uint4*)(sm + base + LKBUF + r * LP + c * 16) = *((const uint4*)(g_Kl + gi) + c);
        }
    };
    stageK(0, 0);
    __syncthreads();

    const int r0 = lane >> 2;
    const int irow0 = i0 + wid * 16 + r0;
    float m_run[2] = {-3.402823466e38f, -3.402823466e38f};
    float l_run[2] = {0.0f, 0.0f};

    const uint32_t b_row = (uint32_t)((lane & 7) + (lane >> 4) * 8);
    const uint32_t b_kb  = (uint32_t)(((lane >> 3) & 1) * 16);

    for (int c = 0; c < 32; c++) {
        const int m0 = c * 64;
        const int buf = (c & 1) * 2 * LKBUF;

        float Cf[8][4];
#pragma unroll
        for (int nf = 0; nf < 8; nf++)
#pragma unroll
            for (int j = 0; j < 4; j++) Cf[nf][j] = 0.0f;

#pragma unroll
        for (int ks = 0; ks < 4; ks++) {
            uint32_t kh[8][2], kl[8][2];
#pragma unroll
            for (int mg = 0; mg < 4; mg++) {
                const uint32_t baddr = smb + buf + (mg * 16 + b_row) * LP + ks * 32 + b_kb;
                uint32_t t4[4];
                ldsm4(baddr, t4);
                kh[mg * 2][0] = t4[0]; kh[mg * 2][1] = t4[1];
                kh[mg * 2 + 1][0] = t4[2]; kh[mg * 2 + 1][1] = t4[3];
                ldsm4(baddr + LKBUF, t4);
                kl[mg * 2][0] = t4[0]; kl[mg * 2][1] = t4[1];
                kl[mg * 2 + 1][0] = t4[2]; kl[mg * 2 + 1][1] = t4[3];
            }
#pragma unroll
            for (int nf = 0; nf < 8; nf++) {
                mma16816(Cf[nf], qh[ks], kh[nf]);
                mma16816(Cf[nf], ql[ks], kh[nf]);
                mma16816(Cf[nf], qh[ks], kl[nf]);
            }
        }

        float mx[2] = {-3.402823466e38f, -3.402823466e38f};
#pragma unroll
        for (int nf = 0; nf < 8; nf++) {
            const int col = m0 + nf * 8 + (lane & 3) * 2;
            const float2 bv0 = *(const float2*)(bias + ((size_t)(b * Ic) + irow0) * Mc + col);
            const float2 bv1 = *(const float2*)(bias + ((size_t)(b * Ic) + irow0 + 8) * Mc + col);
            Cf[nf][0] += bv0.x; Cf[nf][1] += bv0.y;
            Cf[nf][2] += bv1.x; Cf[nf][3] += bv1.y;
            *(float2*)(align + ((size_t)(bh * Ic) + irow0) * Mc + col) =
                make_float2(Cf[nf][0], Cf[nf][1]);
            *(float2*)(align + ((size_t)(bh * Ic) + irow0 + 8) * Mc + col) =
                make_float2(Cf[nf][2], Cf[nf][3]);
            mx[0] = fmaxf(mx[0], fmaxf(Cf[nf][0], Cf[nf][1]));
            mx[1] = fmaxf(mx[1], fmaxf(Cf[nf][2], Cf[nf][3]));
        }
#pragma unroll
        for (int rr = 0; rr < 2; rr++) {
            mx[rr] = fmaxf(mx[rr], __shfl_xor_sync(0xffffffffu, mx[rr], 1));
            mx[rr] = fmaxf(mx[rr], __shfl_xor_sync(0xffffffffu, mx[rr], 2));
            const float mnew = fmaxf(m_run[rr], mx[rr]);
            const float sc = fexp(m_run[rr] - mnew);
            float ps = 0.0f;
#pragma unroll
            for (int nf = 0; nf < 8; nf++)
                ps += fexp(Cf[nf][rr * 2] - mnew) + fexp(Cf[nf][rr * 2 + 1] - mnew);
            ps += __shfl_xor_sync(0xffffffffu, ps, 1);
            ps += __shfl_xor_sync(0xffffffffu, ps, 2);
            l_run[rr] = l_run[rr] * sc + ps;
            m_run[rr] = mnew;
        }

        if (c + 1 < 32) {
            __syncthreads();
            stageK((c + 1) * 64, (1 - (c & 1)) * 2 * LKBUF);
            __syncthreads();
        }
    }

    if ((lane & 3) == 0) {
#pragma unroll
        for (int rr = 0; rr < 2; rr++) {
            g_stats[bh * Ic + irow0 + rr * 8] = make_float2(m_run[rr], 1.0f / l_run[rr]);
        }
    }
}

// ====== pv (EXACT R4, split-O epilogue): normalize align; O = P V ===========
#define PV_PL   0            // Ph [128][LP]
#define PV_PLL  18432        // Pl
#define PV_VH   36864        // Vh [64][LP]
#define PV_VL   46080        // Vl
#define SMEM_PV 55296
__global__ __launch_bounds__(256) void pv_kernel(float* __restrict__ align)
{
    extern __shared__ char smp[];
    const uint32_t smb = smem_u32(smp);
    const int tid = threadIdx.x, wid = tid >> 5, lane = tid & 31;
    const int bh = blockIdx.y, b = bh >> 4, h = bh & 15;
    const int i0 = blockIdx.x * 128;

    int irA[8], mgA[8];
    float2 st[8];
#pragma unroll
    for (int t = 0; t < 8; t++) {
        const int fi = tid + t * 256;
        irA[t] = fi >> 4;
        mgA[t] = (fi & 15) * 4;
        st[t] = g_stats[bh * Ic + i0 + irA[t]];
    }

    float Cf[8][4];
#pragma unroll
    for (int nf = 0; nf < 8; nf++)
#pragma unroll
        for (int j = 0; j < 4; j++) Cf[nf][j] = 0.0f;

    float4 sreg[8];
    auto ldS = [&](int m0) {
#pragma unroll
        for (int t = 0; t < 8; t++)
            sreg[t] = *(const float4*)(align + ((size_t)(bh * Ic) + i0 + irA[t]) * Mc + m0 + mgA[t]);
    };
    ldS(0);

    const uint32_t a_off = (uint32_t)((wid * 16 + (lane & 7) + ((lane >> 3) & 1) * 8) * LP
                                      + (lane >> 4) * 16);
    const uint32_t vb_r = (uint32_t)(((lane >> 3) & 1) * 8 + (lane & 7));
    const uint32_t vb_c = (uint32_t)(((lane >> 4) & 1) * 16);

    for (int c = 0; c < 32; c++) {
        const int m0 = c * 64;

        // stage P: exp + normalize, write final align, split to smem
#pragma unroll
        for (int t = 0; t < 8; t++) {
            float4 s4 = sreg[t];
            float4 p4;
            p4.x = fexp(s4.x - st[t].x) * st[t].y;
            p4.y = fexp(s4.y - st[t].x) * st[t].y;
            p4.z = fexp(s4.z - st[t].x) * st[t].y;
            p4.w = fexp(s4.w - st[t].x) * st[t].y;
            *(float4*)(align + ((size_t)(bh * Ic) + i0 + irA[t]) * Mc + m0 + mgA[t]) = p4;
            __nv_bfloat162 h0, l0, h1, l1;
            cvt_split(p4.x, p4.y, h0, l0);
            cvt_split(p4.z, p4.w, h1, l1);
            const int base = irA[t] * LP + mgA[t] * 2;
            *(__nv_bfloat162*)(smp + PV_PL + base)      = h0;
            *(__nv_bfloat162*)(smp + PV_PL + base + 4)  = h1;
            *(__nv_bfloat162*)(smp + PV_PLL + base)     = l0;
            *(__nv_bfloat162*)(smp + PV_PLL + base + 4) = l1;
        }
        // stage V
#pragma unroll
        for (int t = 0; t < 2; t++) {
            const int fi = tid + t * 256;
            const int r = fi >> 3, cc = fi & 7;
            const size_t gi = ((size_t)bh * Mc + m0 + r) * 64;
            *(uint4*)(smp + PV_VH + r * LP + cc * 16) = *((const uint4*)(g_Vh + gi) + cc);
            *(uint4*)(smp + PV_VL + r * LP + cc * 16) = *((const uint4*)(g_Vl + gi) + cc);
        }
        __syncthreads();

        if (c + 1 < 32) ldS((c + 1) * 64);   // prefetch next S (hidden under MMA)

#pragma unroll
        for (int ks = 0; ks < 4; ks++) {
            uint32_t ph[4], pl[4];
            ldsm4(smb + PV_PL + a_off + ks * 32, ph);
            ldsm4(smb + PV_PLL + a_off + ks * 32, pl);
            uint32_t vh[8][2], vl[8][2];
#pragma unroll
            for (int q = 0; q < 4; q++) {
                const uint32_t vaddr = smb + PV_VH + (ks * 16 + vb_r) * LP + q * 32 + vb_c;
                uint32_t t4[4];
                ldsm4t(vaddr, t4);
                vh[q * 2][0] = t4[0]; vh[q * 2][1] = t4[1];
                vh[q * 2 + 1][0] = t4[2]; vh[q * 2 + 1][1] = t4[3];
                ldsm4t(vaddr + (PV_VL - PV_VH), t4);
                vl[q * 2][0] = t4[0]; vl[q * 2][1] = t4[1];
                vl[q * 2 + 1][0] = t4[2]; vl[q * 2 + 1][1] = t4[3];
            }
#pragma unroll
            for (int nf = 0; nf < 8; nf++) {
                mma16816(Cf[nf], ph, vh[nf]);
                mma16816(Cf[nf], pl, vh[nf]);
                mma16816(Cf[nf], ph, vl[nf]);
            }
        }
        __syncthreads();
    }

    // epilogue: O -> g_Oh/g_Ol split bf16, layout [b][i][h*64+d]
#pragma unroll
    for (int nf = 0; nf < 8; nf++) {
        const int d = nf * 8 + (lane & 3) * 2;
        const int rg = i0 + wid * 16 + (lane >> 2);
        const size_t idx0 = ((size_t)(b * Ic) + rg) * Dc + h * 64 + d;
        const size_t idx1 = ((size_t)(b * Ic) + rg + 8) * Dc + h * 64 + d;
        __nv_bfloat162 hh, ll;
        cvt_split(Cf[nf][0], Cf[nf][1], hh, ll);
        *(__nv_bfloat162*)(g_Oh + idx0) = hh;
        *(__nv_bfloat162*)(g_Ol + idx0) = ll;
        cvt_split(Cf[nf][2], Cf[nf][3], hh, ll);
        *(__nv_bfloat162*)(g_Oh + idx1) = hh;
        *(__nv_bfloat162*)(g_Ol + idx1) = ll;
    }
}

// ---------------- launch ----------------------------------------------------
extern "C" void kernel_launch(void* const* d_in, const int* in_sizes, int n_in,
                              void* d_out, int out_size)
{
    const float* input  = (const float*)d_in[0];
    const float* memory = (const float*)d_in[1];
    const float* bias   = (const float*)d_in[2];
    const float* Wq     = (const float*)d_in[3];
    const float* Wk     = (const float*)d_in[4];
    const float* Wv     = (const float*)d_in[5];
    const float* Wo     = (const float*)d_in[6];

    float* out   = (float*)d_out;                  // [B,I,D]
    float* align = out + (size_t)Bc * Ic * Dc;     // [B,H,I,M]

    static int attr_done = 0;
    if (!attr_done) {
        cudaFuncSetAttribute(qkv_kernel, cudaFuncAttributeMaxDynamicSharedMemorySize, SMEM_GEMM);
        cudaFuncSetAttribute(out_kernel, cudaFuncAttributeMaxDynamicSharedMemorySize, SMEM_GEMM);
        cudaFuncSetAttribute(pv_kernel,  cudaFuncAttributeMaxDynamicSharedMemorySize, SMEM_PV);
        attr_done = 1;
    }

    split_kernel<<<dim3(1024, 6), 256>>>(input, memory, Wq, Wk, Wv, Wo);

    dim3 gqkv(Dc / 128, (Bc * Ic) / 128, 3);       // (8, 32, 3)
    qkv_kernel<<<gqkv, 256, SMEM_GEMM>>>();

    logits_kernel<<<dim3(Ic / 128, BHc), 256>>>(bias, align);

    pv_kernel<<<dim3(Ic / 128, BHc), 256, SMEM_PV>>>(align);

    out_kernel<<<dim3(Dc / 128, (Bc * Ic) / 128), 256, SMEM_GEMM>>>(out);
}